// round 10
// baseline (speedup 1.0000x reference)
#include <cuda_runtime.h>
#include <cuda_bf16.h>
#include <math.h>
#include <stdint.h>

#define S_TOK 4096
#define D_DIM 2048

// ---------------- scratch (no allocation allowed -> __device__ globals) ----------
__device__ __nv_bfloat16 g_xh[(size_t)S_TOK * D_DIM];
__device__ __nv_bfloat16 g_xl[(size_t)S_TOK * D_DIM];
__device__ __nv_bfloat16 g_wqh[(size_t)D_DIM * D_DIM];
__device__ __nv_bfloat16 g_wql[(size_t)D_DIM * D_DIM];
__device__ __nv_bfloat16 g_wkh[(size_t)D_DIM * D_DIM];
__device__ __nv_bfloat16 g_wkl[(size_t)D_DIM * D_DIM];
__device__ __nv_bfloat16 g_wvh[(size_t)D_DIM * D_DIM];
__device__ __nv_bfloat16 g_wvl[(size_t)D_DIM * D_DIM];
__device__ __nv_bfloat16 g_qh[(size_t)S_TOK * D_DIM];
__device__ __nv_bfloat16 g_ql[(size_t)S_TOK * D_DIM];
__device__ __nv_bfloat16 g_kh[(size_t)S_TOK * D_DIM];
__device__ __nv_bfloat16 g_kl[(size_t)S_TOK * D_DIM];
__device__ __nv_bfloat16 g_vth[(size_t)D_DIM * S_TOK];   // vT [D, S]
__device__ __nv_bfloat16 g_vtl[(size_t)D_DIM * S_TOK];
__device__ float         g_sc[(size_t)S_TOK * S_TOK];    // scores fp32
__device__ __nv_bfloat16 g_ah[(size_t)S_TOK * S_TOK];    // attn hi
__device__ __nv_bfloat16 g_al[(size_t)S_TOK * S_TOK];    // attn lo

// ============================ PTX helpers (base-arch only) ========================
__device__ __forceinline__ uint32_t smem_u32(const void* p) {
    uint32_t a;
    asm("{ .reg .u64 t; cvta.to.shared.u64 t, %1; cvt.u32.u64 %0, t; }" : "=r"(a) : "l"(p));
    return a;
}
#define CP_ASYNC16(dst, src) \
    asm volatile("cp.async.cg.shared.global [%0], [%1], 16;" :: "r"(dst), "l"(src) : "memory")
#define CP_COMMIT() asm volatile("cp.async.commit_group;" ::: "memory")
#define CP_WAIT2()  asm volatile("cp.async.wait_group 2;" ::: "memory")
#define CP_WAIT1()  asm volatile("cp.async.wait_group 1;" ::: "memory")
#define CP_WAIT0()  asm volatile("cp.async.wait_group 0;" ::: "memory")

__device__ __forceinline__ void ldsm_x4(uint32_t addr, uint32_t* r) {
    asm volatile("ldmatrix.sync.aligned.m8n8.x4.shared.b16 {%0,%1,%2,%3}, [%4];"
                 : "=r"(r[0]), "=r"(r[1]), "=r"(r[2]), "=r"(r[3]) : "r"(addr));
}
__device__ __forceinline__ void mma_bf16(float* d, const uint32_t* a, const uint32_t* b) {
    asm volatile(
        "mma.sync.aligned.m16n8k16.row.col.f32.bf16.bf16.f32 "
        "{%0,%1,%2,%3}, {%4,%5,%6,%7}, {%8,%9}, {%0,%1,%2,%3};"
        : "+f"(d[0]), "+f"(d[1]), "+f"(d[2]), "+f"(d[3])
        : "r"(a[0]), "r"(a[1]), "r"(a[2]), "r"(a[3]), "r"(b[0]), "r"(b[1]));
}
// 64-byte-row swizzle (8 rows x 64B atom): XOR bits[5:4] with bits[8:7]
__device__ __forceinline__ uint32_t sw64(uint32_t off) { return off ^ ((off >> 3) & 0x30); }

// ============================ bf16 split-precision NT GEMM ========================
// C[M,N] = (Ah+Al)[M,K] * (Bh+Bl)[N,K]^T  (drop Al*Bl).
// CTA tile 256x128, warp tile 64x64 (8 warps, 4x2), K-chunk 32.
// 4-stage cp.async pipeline, single barrier per chunk, 192KB smem (1 CTA/SM).
// mode: 0 full, 1 causal tile-skip (n0 >= m0+256), 2 triangular K (kend = m0+256)
// epi:  0 write fp32 C, 1 write hi/lo bf16 (Ch, Cl)
#define KC        32
#define A_TILE_B  16384              // 256 rows x 32 bf16 (64B/row)
#define B_TILE_B  8192               // 128 rows x 32 bf16
#define STAGE_B   (2 * A_TILE_B + 2 * B_TILE_B)   // Ah, Al, Bh, Bl = 48KB
#define OFF_AL    A_TILE_B
#define OFF_BH    (2 * A_TILE_B)
#define OFF_BL    (2 * A_TILE_B + B_TILE_B)
#define NSTAGE    4
#define GEMM_SMEM (NSTAGE * STAGE_B) // 192KB

__device__ __forceinline__ void issue_tileA(const __nv_bfloat16* __restrict__ g,
                                            int row0, int ld, int k0,
                                            uint32_t sbase, int tid) {
    #pragma unroll
    for (int it = 0; it < 4; it++) {
        int u = tid + it * 256;          // 0..1023 16-byte units (256 rows x 4)
        int r = u >> 2, s = u & 3;
        CP_ASYNC16(sbase + sw64(r * 64 + s * 16),
                   g + (size_t)(row0 + r) * ld + k0 + s * 8);
    }
}
__device__ __forceinline__ void issue_tileB(const __nv_bfloat16* __restrict__ g,
                                            int row0, int ld, int k0,
                                            uint32_t sbase, int tid) {
    #pragma unroll
    for (int it = 0; it < 2; it++) {
        int u = tid + it * 256;          // 0..511 (128 rows x 4)
        int r = u >> 2, s = u & 3;
        CP_ASYNC16(sbase + sw64(r * 64 + s * 16),
                   g + (size_t)(row0 + r) * ld + k0 + s * 8);
    }
}
__device__ __forceinline__ void issue_chunk(
    const __nv_bfloat16* Ah, const __nv_bfloat16* Al,
    const __nv_bfloat16* Bh, const __nv_bfloat16* Bl,
    int m0, int n0, int K, int k0, uint32_t st, int tid) {
    issue_tileA(Ah, m0, K, k0, st,          tid);
    issue_tileA(Al, m0, K, k0, st + OFF_AL, tid);
    issue_tileB(Bh, n0, K, k0, st + OFF_BH, tid);
    issue_tileB(Bl, n0, K, k0, st + OFF_BL, tid);
    CP_COMMIT();
}

__global__ void __launch_bounds__(256) gemm_nt_tc(
    const __nv_bfloat16* __restrict__ Ah, const __nv_bfloat16* __restrict__ Al,
    const __nv_bfloat16* __restrict__ Bh, const __nv_bfloat16* __restrict__ Bl,
    float* __restrict__ C, __nv_bfloat16* __restrict__ Ch, __nv_bfloat16* __restrict__ Cl,
    int M, int N, int K, int mode, int epi)
{
    extern __shared__ char smem[];
    const int tid = threadIdx.x, wid = tid >> 5, lane = tid & 31;
    const int nb = blockIdx.x, mb = blockIdx.y;
    const int m0 = mb * 256, n0 = nb * 128;
    if (mode == 1 && n0 >= m0 + 256) return;
    const int kend = (mode == 2) ? (m0 + 256 < K ? m0 + 256 : K) : K;
    const int nch = kend / KC;          // >= 8 always here

    const uint32_t sbase = smem_u32(smem);
    const int wm = wid >> 1;            // 0..3 : 64-row band
    const int wn = wid & 1;             // 0..1 : 64-col band

    float acc[4][8][4];
    #pragma unroll
    for (int mf = 0; mf < 4; mf++)
        #pragma unroll
        for (int nf = 0; nf < 8; nf++)
            #pragma unroll
            for (int c = 0; c < 4; c++) acc[mf][nf][c] = 0.f;

    // prologue: chunks 0..2 into stages 0..2
    #pragma unroll
    for (int pre = 0; pre < 3; pre++)
        issue_chunk(Ah, Al, Bh, Bl, m0, n0, K, pre * KC, sbase + pre * STAGE_B, tid);

    // per-lane ldmatrix addressing (byte offsets, 64B rows, sw64)
    const int a_row = wm * 64 + (lane & 15);
    const int a_col = ((lane >> 4) & 1) * 16;
    const int b_idx = lane >> 3;
    const int b_row = wn * 64 + ((b_idx >> 1) * 8) + (lane & 7);
    const int b_col = (b_idx & 1) * 16;

    for (int i = 0; i < nch; i++) {
        if (i + 3 <= nch) { CP_WAIT2(); }
        else if (i == nch - 2) { CP_WAIT1(); }
        else { CP_WAIT0(); }
        __syncthreads();
        // single barrier: stage (i+3)%4 == (i-1)%4 was fully read before this barrier
        if (i + 3 < nch)
            issue_chunk(Ah, Al, Bh, Bl, m0, n0, K, (i + 3) * KC,
                        sbase + ((i + 3) % NSTAGE) * STAGE_B, tid);

        const uint32_t buf = sbase + (i % NSTAGE) * STAGE_B;
        #pragma unroll
        for (int ks = 0; ks < 2; ks++) {
            const int kc = ks * 32;     // byte offset of k16 step within 64B row
            uint32_t ah[4][4], al[4][4];
            #pragma unroll
            for (int mf = 0; mf < 4; mf++) {
                ldsm_x4(buf + sw64((a_row + mf * 16) * 64 + kc + a_col), ah[mf]);
                ldsm_x4(buf + OFF_AL + sw64((a_row + mf * 16) * 64 + kc + a_col), al[mf]);
            }
            #pragma unroll
            for (int p = 0; p < 4; p++) {
                uint32_t bh[4], bl[4];
                ldsm_x4(buf + OFF_BH + sw64((b_row + p * 16) * 64 + kc + b_col), bh);
                ldsm_x4(buf + OFF_BL + sw64((b_row + p * 16) * 64 + kc + b_col), bl);
                // pass-major ordering: 8 independent accs between same-acc MMAs
                #pragma unroll
                for (int mf = 0; mf < 4; mf++)
                    #pragma unroll
                    for (int h = 0; h < 2; h++)
                        mma_bf16(acc[mf][2 * p + h], ah[mf], &bh[2 * h]);   // Ah*Bh
                #pragma unroll
                for (int mf = 0; mf < 4; mf++)
                    #pragma unroll
                    for (int h = 0; h < 2; h++)
                        mma_bf16(acc[mf][2 * p + h], ah[mf], &bl[2 * h]);   // Ah*Bl
                #pragma unroll
                for (int mf = 0; mf < 4; mf++)
                    #pragma unroll
                    for (int h = 0; h < 2; h++)
                        mma_bf16(acc[mf][2 * p + h], al[mf], &bh[2 * h]);   // Al*Bh
            }
        }
    }

    // epilogue
    const int em = m0 + wm * 64 + (lane >> 2);
    const int en = n0 + wn * 64 + (lane & 3) * 2;
    #pragma unroll
    for (int mf = 0; mf < 4; mf++) {
        #pragma unroll
        for (int nf = 0; nf < 8; nf++) {
            const int m = em + mf * 16;
            const int n = en + nf * 8;
            const float* d = acc[mf][nf];
            if (epi == 0) {
                float* r0 = C + (size_t)m * N + n;
                float* r1 = C + (size_t)(m + 8) * N + n;
                r0[0] = d[0]; r0[1] = d[1];
                r1[0] = d[2]; r1[1] = d[3];
            } else {
                #pragma unroll
                for (int hrow = 0; hrow < 2; hrow++) {
                    const int mm = m + hrow * 8;
                    float f0 = d[hrow * 2 + 0], f1 = d[hrow * 2 + 1];
                    __nv_bfloat16 h0 = __float2bfloat16(f0);
                    __nv_bfloat16 h1 = __float2bfloat16(f1);
                    __nv_bfloat162 hv; hv.x = h0; hv.y = h1;
                    __nv_bfloat162 lv;
                    lv.x = __float2bfloat16(f0 - __bfloat162float(h0));
                    lv.y = __float2bfloat16(f1 - __bfloat162float(h1));
                    *(__nv_bfloat162*)(Ch + (size_t)mm * N + n) = hv;
                    *(__nv_bfloat162*)(Cl + (size_t)mm * N + n) = lv;
                }
            }
        }
    }
}

// ============================ fp32 -> hi/lo bf16 split ============================
__global__ __launch_bounds__(256) void split_fp32(const float* __restrict__ in,
                                                  __nv_bfloat16* __restrict__ h,
                                                  __nv_bfloat16* __restrict__ l,
                                                  size_t n4)
{
    size_t i = (size_t)blockIdx.x * 256 + threadIdx.x;
    size_t stride = (size_t)gridDim.x * 256;
    for (; i < n4; i += stride) {
        float4 f = ((const float4*)in)[i];
        __nv_bfloat16 hv[4], lv[4];
        float fv[4] = { f.x, f.y, f.z, f.w };
        #pragma unroll
        for (int c = 0; c < 4; c++) {
            hv[c] = __float2bfloat16(fv[c]);
            lv[c] = __float2bfloat16(fv[c] - __bfloat162float(hv[c]));
        }
        ((uint2*)h)[i] = *(uint2*)hv;
        ((uint2*)l)[i] = *(uint2*)lv;
    }
}

// ============================ softmax + dropout -> hi/lo bf16 =====================
__global__ __launch_bounds__(256) void softmax_dropout_kernel(
    const float* __restrict__ scores, const float* __restrict__ drop_mask,
    __nv_bfloat16* __restrict__ ah, __nv_bfloat16* __restrict__ al)
{
    const int i = blockIdx.x;
    const int tid = threadIdx.x;
    const int nvalid = i + 1;
    const float scale = rsqrtf((float)D_DIM);

    const float* row = scores + (size_t)i * S_TOK;
    const float* mrow = drop_mask + (size_t)i * S_TOK;
    __nv_bfloat16* hrow = ah + (size_t)i * S_TOK;
    __nv_bfloat16* lrow = al + (size_t)i * S_TOK;

    __shared__ float red[256];

    float lmax = -INFINITY;
    for (int j = tid; j < nvalid; j += 256) lmax = fmaxf(lmax, row[j] * scale);
    red[tid] = lmax;
    __syncthreads();
    for (int s = 128; s > 0; s >>= 1) {
        if (tid < s) red[tid] = fmaxf(red[tid], red[tid + s]);
        __syncthreads();
    }
    const float m = red[0];
    __syncthreads();

    float lsum = 0.f;
    for (int j = tid; j < nvalid; j += 256) lsum += __expf(row[j] * scale - m);
    red[tid] = lsum;
    __syncthreads();
    for (int s = 128; s > 0; s >>= 1) {
        if (tid < s) red[tid] += red[tid + s];
        __syncthreads();
    }
    const float inv_z = 1.0f / red[0];

    const int zend = (((i >> 8) + 1) << 8);   // pad to 256-boundary for triangular GEMM
    for (int j = tid; j < zend; j += 256) {
        float out = 0.f;
        if (j < nvalid) out = __expf(row[j] * scale - m) * inv_z * mrow[j];
        __nv_bfloat16 h = __float2bfloat16(out);
        hrow[j] = h;
        lrow[j] = __float2bfloat16(out - __bfloat162float(h));
    }
}

// =================================== launch =======================================
extern "C" void kernel_launch(void* const* d_in, const int* in_sizes, int n_in,
                              void* d_out, int out_size)
{
    const float* x  = (const float*)d_in[0];
    const float* Wq = (const float*)d_in[1];
    const float* Wk = (const float*)d_in[2];
    const float* Wv = (const float*)d_in[3];
    const float* dm = (const float*)d_in[4];
    float* out = (float*)d_out;

    __nv_bfloat16 *xh, *xl, *wqh, *wql, *wkh, *wkl, *wvh, *wvl;
    __nv_bfloat16 *qh, *ql, *kh, *kl, *vth, *vtl, *ah, *al;
    float *sc;
    cudaGetSymbolAddress((void**)&xh,  g_xh);   cudaGetSymbolAddress((void**)&xl,  g_xl);
    cudaGetSymbolAddress((void**)&wqh, g_wqh);  cudaGetSymbolAddress((void**)&wql, g_wql);
    cudaGetSymbolAddress((void**)&wkh, g_wkh);  cudaGetSymbolAddress((void**)&wkl, g_wkl);
    cudaGetSymbolAddress((void**)&wvh, g_wvh);  cudaGetSymbolAddress((void**)&wvl, g_wvl);
    cudaGetSymbolAddress((void**)&qh,  g_qh);   cudaGetSymbolAddress((void**)&ql,  g_ql);
    cudaGetSymbolAddress((void**)&kh,  g_kh);   cudaGetSymbolAddress((void**)&kl,  g_kl);
    cudaGetSymbolAddress((void**)&vth, g_vth);  cudaGetSymbolAddress((void**)&vtl, g_vtl);
    cudaGetSymbolAddress((void**)&ah,  g_ah);   cudaGetSymbolAddress((void**)&al,  g_al);
    cudaGetSymbolAddress((void**)&sc,  g_sc);

    cudaFuncSetAttribute(gemm_nt_tc, cudaFuncAttributeMaxDynamicSharedMemorySize, GEMM_SMEM);

    // 0) split inputs to hi/lo bf16
    split_fp32<<<512, 256>>>(x,  xh,  xl,  (size_t)S_TOK * D_DIM / 4);
    split_fp32<<<512, 256>>>(Wq, wqh, wql, (size_t)D_DIM * D_DIM / 4);
    split_fp32<<<512, 256>>>(Wk, wkh, wkl, (size_t)D_DIM * D_DIM / 4);
    split_fp32<<<512, 256>>>(Wv, wvh, wvl, (size_t)D_DIM * D_DIM / 4);

    // 1) q = x@Wq^T, k = x@Wk^T (epi -> hi/lo), vT = Wv @ x^T -> [D, S]
    dim3 gProj(D_DIM / 128, S_TOK / 256);
    gemm_nt_tc<<<gProj, 256, GEMM_SMEM>>>(xh, xl, wqh, wql, nullptr, qh, ql,
                                          S_TOK, D_DIM, D_DIM, 0, 1);
    gemm_nt_tc<<<gProj, 256, GEMM_SMEM>>>(xh, xl, wkh, wkl, nullptr, kh, kl,
                                          S_TOK, D_DIM, D_DIM, 0, 1);
    dim3 gVT(S_TOK / 128, D_DIM / 256);
    gemm_nt_tc<<<gVT, 256, GEMM_SMEM>>>(wvh, wvl, xh, xl, nullptr, vth, vtl,
                                        D_DIM, S_TOK, D_DIM, 0, 1);

    // 2) scores = q @ k^T (causal tile-skip, epi fp32)
    dim3 gScore(S_TOK / 128, S_TOK / 256);
    gemm_nt_tc<<<gScore, 256, GEMM_SMEM>>>(qh, ql, kh, kl, sc, nullptr, nullptr,
                                           S_TOK, S_TOK, D_DIM, 1, 0);

    // 3) softmax + dropout -> attn hi/lo (zero-padded to 256-boundary)
    softmax_dropout_kernel<<<S_TOK, 256>>>(sc, dm, ah, al);

    // 4) out = attn @ (vT)^T (triangular K, epi fp32)
    dim3 gOut(D_DIM / 128, S_TOK / 256);
    gemm_nt_tc<<<gOut, 256, GEMM_SMEM>>>(ah, al, vth, vtl, out, nullptr, nullptr,
                                         S_TOK, D_DIM, S_TOK, 2, 0);
}

// round 11
// speedup vs baseline: 2.8110x; 2.8110x over previous
#include <cuda_runtime.h>
#include <cuda_fp16.h>
#include <math.h>
#include <stdint.h>

#define S_TOK 4096
#define D_DIM 2048

// ---------------- scratch (no allocation allowed -> __device__ globals) ----------
__device__ __half g_x16[(size_t)S_TOK * D_DIM];
__device__ __half g_wq16[(size_t)D_DIM * D_DIM];
__device__ __half g_wk16[(size_t)D_DIM * D_DIM];
__device__ __half g_wv16[(size_t)D_DIM * D_DIM];
__device__ __half g_q16[(size_t)S_TOK * D_DIM];
__device__ __half g_k16[(size_t)S_TOK * D_DIM];
__device__ __half g_vt16[(size_t)D_DIM * S_TOK];   // vT [D, S]
__device__ float  g_sc[(size_t)S_TOK * S_TOK];     // scores fp32
__device__ __half g_a16[(size_t)S_TOK * S_TOK];    // attn fp16

// ============================ PTX helpers (base-arch only) ========================
__device__ __forceinline__ uint32_t smem_u32(const void* p) {
    uint32_t a;
    asm("{ .reg .u64 t; cvta.to.shared.u64 t, %1; cvt.u32.u64 %0, t; }" : "=r"(a) : "l"(p));
    return a;
}
#define CP_ASYNC16(dst, src) \
    asm volatile("cp.async.cg.shared.global [%0], [%1], 16;" :: "r"(dst), "l"(src) : "memory")
#define CP_COMMIT() asm volatile("cp.async.commit_group;" ::: "memory")
#define CP_WAIT1()  asm volatile("cp.async.wait_group 1;" ::: "memory")
#define CP_WAIT0()  asm volatile("cp.async.wait_group 0;" ::: "memory")

__device__ __forceinline__ void ldsm_x4(uint32_t addr, uint32_t* r) {
    asm volatile("ldmatrix.sync.aligned.m8n8.x4.shared.b16 {%0,%1,%2,%3}, [%4];"
                 : "=r"(r[0]), "=r"(r[1]), "=r"(r[2]), "=r"(r[3]) : "r"(addr));
}
__device__ __forceinline__ void mma_f16(float* d, const uint32_t* a, const uint32_t* b) {
    asm volatile(
        "mma.sync.aligned.m16n8k16.row.col.f32.f16.f16.f32 "
        "{%0,%1,%2,%3}, {%4,%5,%6,%7}, {%8,%9}, {%0,%1,%2,%3};"
        : "+f"(d[0]), "+f"(d[1]), "+f"(d[2]), "+f"(d[3])
        : "r"(a[0]), "r"(a[1]), "r"(a[2]), "r"(a[3]), "r"(b[0]), "r"(b[1]));
}
__device__ __forceinline__ uint32_t sw128(uint32_t off) { return off ^ ((off >> 3) & 0x70); }

// ============================ fp16 NT GEMM ========================================
// C[M,N] = A[M,K] * B[N,K]^T, fp16 inputs, fp32 accum. Tile 128x128, K-chunk 64.
// Double-buffered cp.async (round-4 structure), 32KB/stage -> 64KB smem, 2 CTAs/SM.
// mode: 0 full, 1 causal tile-skip (nb > mb), 2 triangular K (kend = m0+128)
// epi:  0 write fp32 C, 1 write fp16 Ch
#define KC       64
#define TILE_B   16384               // 128 rows x 64 fp16 (128B/row)
#define STAGE_B  (2 * TILE_B)        // A, B = 32KB
#define GEMM_SMEM (2 * STAGE_B)      // 64KB

__device__ __forceinline__ void issue_tile64(const __half* __restrict__ g,
                                             int row0, int ld, int k0,
                                             uint32_t sbase, int tid) {
    #pragma unroll
    for (int it = 0; it < 4; it++) {
        int u = tid + it * 256;          // 0..1023 16-byte units
        int r = u >> 3, s = u & 7;
        CP_ASYNC16(sbase + sw128(r * 128 + s * 16),
                   g + (size_t)(row0 + r) * ld + k0 + s * 8);
    }
}

__global__ void __launch_bounds__(256, 2) gemm_nt_f16(
    const __half* __restrict__ A, const __half* __restrict__ B,
    float* __restrict__ C, __half* __restrict__ Ch,
    int M, int N, int K, int mode, int epi)
{
    extern __shared__ char smem[];
    const int tid = threadIdx.x, wid = tid >> 5, lane = tid & 31;
    const int nb = blockIdx.x, mb = blockIdx.y;
    if (mode == 1 && nb > mb) return;
    const int m0 = mb * 128, n0 = nb * 128;
    const int kend = (mode == 2) ? (m0 + 128 < K ? m0 + 128 : K) : K;
    const int nch = kend >> 6;

    const uint32_t sbase = smem_u32(smem);
    const int wm = wid >> 1;            // 0..3 : 32-row band
    const int wn = wid & 1;             // 0..1 : 64-col band

    float acc[2][8][4];
    #pragma unroll
    for (int mf = 0; mf < 2; mf++)
        #pragma unroll
        for (int nf = 0; nf < 8; nf++)
            #pragma unroll
            for (int c = 0; c < 4; c++) acc[mf][nf][c] = 0.f;

    // preload chunk 0 into buffer 0
    issue_tile64(A, m0, K, 0, sbase,          tid);
    issue_tile64(B, n0, K, 0, sbase + TILE_B, tid);
    CP_COMMIT();

    // per-lane ldmatrix addressing (byte offsets within a 128x64fp16 tile)
    const int a_row = wm * 32 + (lane & 15);
    const int a_col = ((lane >> 4) & 1) * 16;
    const int b_idx = lane >> 3;
    const int b_row = wn * 64 + ((b_idx >> 1) * 8) + (lane & 7);
    const int b_col = (b_idx & 1) * 16;

    for (int i = 0; i < nch; i++) {
        if (i + 1 < nch) {
            const uint32_t nbuf = sbase + ((i + 1) & 1) * STAGE_B;
            const int k1 = (i + 1) << 6;
            issue_tile64(A, m0, K, k1, nbuf,          tid);
            issue_tile64(B, n0, K, k1, nbuf + TILE_B, tid);
            CP_COMMIT();
            CP_WAIT1();
        } else {
            CP_WAIT0();
        }
        __syncthreads();

        const uint32_t buf = sbase + (i & 1) * STAGE_B;
        #pragma unroll
        for (int ks = 0; ks < 4; ks++) {
            const int kc = ks * 32;     // byte offset of k16 step within 128B row
            uint32_t a[2][4];
            ldsm_x4(buf + sw128(a_row * 128 + kc + a_col), a[0]);
            ldsm_x4(buf + sw128((a_row + 16) * 128 + kc + a_col), a[1]);
            #pragma unroll
            for (int p = 0; p < 4; p++) {
                uint32_t b[4];
                ldsm_x4(buf + TILE_B + sw128((b_row + p * 16) * 128 + kc + b_col), b);
                #pragma unroll
                for (int mf = 0; mf < 2; mf++)
                    #pragma unroll
                    for (int h = 0; h < 2; h++)
                        mma_f16(acc[mf][2 * p + h], a[mf], &b[2 * h]);
            }
        }
        __syncthreads();
    }

    // epilogue: thread owns rows (m, m+8), 2 consecutive cols per frag
    const int em = m0 + wm * 32 + (lane >> 2);
    const int en = n0 + wn * 64 + (lane & 3) * 2;
    #pragma unroll
    for (int mf = 0; mf < 2; mf++) {
        #pragma unroll
        for (int nf = 0; nf < 8; nf++) {
            const int m = em + mf * 16;
            const int n = en + nf * 8;
            const float* d = acc[mf][nf];
            if (epi == 0) {
                float* r0 = C + (size_t)m * N + n;
                float* r1 = C + (size_t)(m + 8) * N + n;
                r0[0] = d[0]; r0[1] = d[1];
                r1[0] = d[2]; r1[1] = d[3];
            } else {
                __half2 h0; h0.x = __float2half(d[0]); h0.y = __float2half(d[1]);
                __half2 h1; h1.x = __float2half(d[2]); h1.y = __float2half(d[3]);
                *(__half2*)(Ch + (size_t)m * N + n) = h0;
                *(__half2*)(Ch + (size_t)(m + 8) * N + n) = h1;
            }
        }
    }
}

// ============================ fp32 -> fp16 convert ================================
__global__ __launch_bounds__(256) void conv_fp16(const float* __restrict__ in,
                                                 __half* __restrict__ h, size_t n4)
{
    size_t i = (size_t)blockIdx.x * 256 + threadIdx.x;
    size_t stride = (size_t)gridDim.x * 256;
    for (; i < n4; i += stride) {
        float4 f = ((const float4*)in)[i];
        __half hv[4];
        hv[0] = __float2half(f.x); hv[1] = __float2half(f.y);
        hv[2] = __float2half(f.z); hv[3] = __float2half(f.w);
        ((uint2*)h)[i] = *(uint2*)hv;
    }
}

// ============================ softmax + dropout -> fp16 ===========================
// Row i: attn[j] = exp(s*scale - m)/Z * mask[j] for j<=i; zeros to 128-boundary.
__global__ __launch_bounds__(256) void softmax_dropout_kernel(
    const float* __restrict__ scores, const float* __restrict__ drop_mask,
    __half* __restrict__ attn)
{
    const int i = blockIdx.x;
    const int tid = threadIdx.x;
    const int nvalid = i + 1;
    const float scale = rsqrtf((float)D_DIM);

    const float* row = scores + (size_t)i * S_TOK;
    const float* mrow = drop_mask + (size_t)i * S_TOK;
    __half* arow = attn + (size_t)i * S_TOK;

    __shared__ float red[256];

    float lmax = -INFINITY;
    for (int j = tid; j < nvalid; j += 256) lmax = fmaxf(lmax, row[j] * scale);
    red[tid] = lmax;
    __syncthreads();
    for (int s = 128; s > 0; s >>= 1) {
        if (tid < s) red[tid] = fmaxf(red[tid], red[tid + s]);
        __syncthreads();
    }
    const float m = red[0];
    __syncthreads();

    float lsum = 0.f;
    for (int j = tid; j < nvalid; j += 256) lsum += __expf(row[j] * scale - m);
    red[tid] = lsum;
    __syncthreads();
    for (int s = 128; s > 0; s >>= 1) {
        if (tid < s) red[tid] += red[tid + s];
        __syncthreads();
    }
    const float inv_z = 1.0f / red[0];

    const int zend = (((i >> 7) + 1) << 7);   // pad to 128-boundary for triangular GEMM
    for (int j = tid; j < zend; j += 256) {
        float out = 0.f;
        if (j < nvalid) out = __expf(row[j] * scale - m) * inv_z * mrow[j];
        arow[j] = __float2half(out);
    }
}

// =================================== launch =======================================
extern "C" void kernel_launch(void* const* d_in, const int* in_sizes, int n_in,
                              void* d_out, int out_size)
{
    const float* x  = (const float*)d_in[0];
    const float* Wq = (const float*)d_in[1];
    const float* Wk = (const float*)d_in[2];
    const float* Wv = (const float*)d_in[3];
    const float* dm = (const float*)d_in[4];
    float* out = (float*)d_out;

    __half *x16, *wq16, *wk16, *wv16, *q16, *k16, *vt16, *a16;
    float *sc;
    cudaGetSymbolAddress((void**)&x16,  g_x16);
    cudaGetSymbolAddress((void**)&wq16, g_wq16);
    cudaGetSymbolAddress((void**)&wk16, g_wk16);
    cudaGetSymbolAddress((void**)&wv16, g_wv16);
    cudaGetSymbolAddress((void**)&q16,  g_q16);
    cudaGetSymbolAddress((void**)&k16,  g_k16);
    cudaGetSymbolAddress((void**)&vt16, g_vt16);
    cudaGetSymbolAddress((void**)&a16,  g_a16);
    cudaGetSymbolAddress((void**)&sc,   g_sc);

    cudaFuncSetAttribute(gemm_nt_f16, cudaFuncAttributeMaxDynamicSharedMemorySize, GEMM_SMEM);

    // 0) convert inputs to fp16
    conv_fp16<<<512, 256>>>(x,  x16,  (size_t)S_TOK * D_DIM / 4);
    conv_fp16<<<512, 256>>>(Wq, wq16, (size_t)D_DIM * D_DIM / 4);
    conv_fp16<<<512, 256>>>(Wk, wk16, (size_t)D_DIM * D_DIM / 4);
    conv_fp16<<<512, 256>>>(Wv, wv16, (size_t)D_DIM * D_DIM / 4);

    // 1) q = x@Wq^T, k = x@Wk^T (epi fp16), vT = Wv @ x^T -> [D, S] (epi fp16)
    dim3 gProj(D_DIM / 128, S_TOK / 128);
    gemm_nt_f16<<<gProj, 256, GEMM_SMEM>>>(x16, wq16, nullptr, q16,
                                           S_TOK, D_DIM, D_DIM, 0, 1);
    gemm_nt_f16<<<gProj, 256, GEMM_SMEM>>>(x16, wk16, nullptr, k16,
                                           S_TOK, D_DIM, D_DIM, 0, 1);
    dim3 gVT(S_TOK / 128, D_DIM / 128);
    gemm_nt_f16<<<gVT, 256, GEMM_SMEM>>>(wv16, x16, nullptr, vt16,
                                         D_DIM, S_TOK, D_DIM, 0, 1);

    // 2) scores = q @ k^T (causal tile-skip, epi fp32)
    dim3 gScore(S_TOK / 128, S_TOK / 128);
    gemm_nt_f16<<<gScore, 256, GEMM_SMEM>>>(q16, k16, sc, nullptr,
                                            S_TOK, S_TOK, D_DIM, 1, 0);

    // 3) softmax + dropout -> attn fp16 (zero-padded to 128-boundary)
    softmax_dropout_kernel<<<S_TOK, 256>>>(sc, dm, a16);

    // 4) out = attn @ (vT)^T (triangular K, epi fp32)
    dim3 gOut(D_DIM / 128, S_TOK / 128);
    gemm_nt_f16<<<gOut, 256, GEMM_SMEM>>>(a16, vt16, out, nullptr,
                                          S_TOK, D_DIM, S_TOK, 2, 0);
}

// round 13
// speedup vs baseline: 3.1522x; 1.1214x over previous
#include <cuda_runtime.h>
#include <cuda_fp16.h>
#include <math.h>
#include <stdint.h>

#define S_TOK 4096
#define D_DIM 2048

// ---------------- scratch (no allocation allowed -> __device__ globals) ----------
__device__ __half g_x16[(size_t)S_TOK * D_DIM];
__device__ __half g_wq16[(size_t)D_DIM * D_DIM];
__device__ __half g_wk16[(size_t)D_DIM * D_DIM];
__device__ __half g_wv16[(size_t)D_DIM * D_DIM];
__device__ __half g_q16[(size_t)S_TOK * D_DIM];
__device__ __half g_k16[(size_t)S_TOK * D_DIM];
__device__ __half g_vt16[(size_t)D_DIM * S_TOK];   // vT [D, S]
__device__ float  g_sc[(size_t)S_TOK * S_TOK];     // scores fp32
__device__ __half g_a16[(size_t)S_TOK * S_TOK];    // attn fp16

// ============================ PTX helpers (base-arch only) ========================
__device__ __forceinline__ uint32_t smem_u32(const void* p) {
    uint32_t a;
    asm("{ .reg .u64 t; cvta.to.shared.u64 t, %1; cvt.u32.u64 %0, t; }" : "=r"(a) : "l"(p));
    return a;
}
#define CP_ASYNC16(dst, src) \
    asm volatile("cp.async.cg.shared.global [%0], [%1], 16;" :: "r"(dst), "l"(src) : "memory")
#define CP_COMMIT() asm volatile("cp.async.commit_group;" ::: "memory")
#define CP_WAIT1()  asm volatile("cp.async.wait_group 1;" ::: "memory")
#define CP_WAIT0()  asm volatile("cp.async.wait_group 0;" ::: "memory")

__device__ __forceinline__ void ldsm_x4(uint32_t addr, uint32_t* r) {
    asm volatile("ldmatrix.sync.aligned.m8n8.x4.shared.b16 {%0,%1,%2,%3}, [%4];"
                 : "=r"(r[0]), "=r"(r[1]), "=r"(r[2]), "=r"(r[3]) : "r"(addr));
}
__device__ __forceinline__ void mma_f16(float* d, const uint32_t* a, const uint32_t* b) {
    asm volatile(
        "mma.sync.aligned.m16n8k16.row.col.f32.f16.f16.f32 "
        "{%0,%1,%2,%3}, {%4,%5,%6,%7}, {%8,%9}, {%0,%1,%2,%3};"
        : "+f"(d[0]), "+f"(d[1]), "+f"(d[2]), "+f"(d[3])
        : "r"(a[0]), "r"(a[1]), "r"(a[2]), "r"(a[3]), "r"(b[0]), "r"(b[1]));
}
__device__ __forceinline__ uint32_t sw128(uint32_t off) { return off ^ ((off >> 3) & 0x70); }

// ============================ fp16 NT GEMM core ===================================
#define KC       64
#define TILE_B   16384               // 128 rows x 64 fp16 (128B/row)
#define STAGE_B  (2 * TILE_B)        // A, B = 32KB
#define GEMM_SMEM (2 * STAGE_B)      // 64KB

__device__ __forceinline__ void issue_tile64(const __half* __restrict__ g,
                                             int row0, int ld, int k0,
                                             uint32_t sbase, int tid) {
    #pragma unroll
    for (int it = 0; it < 4; it++) {
        int u = tid + it * 256;          // 0..1023 16-byte units
        int r = u >> 3, s = u & 7;
        CP_ASYNC16(sbase + sw128(r * 128 + s * 16),
                   g + (size_t)(row0 + r) * ld + k0 + s * 8);
    }
}

// C[M,N] = A[M,K] * B[N,K]^T over k in [0, kend). epi: 0 -> fp32 C, 1 -> fp16 Ch.
__device__ __forceinline__ void gemm_core(
    char* smem,
    const __half* __restrict__ A, const __half* __restrict__ B,
    float* __restrict__ C, __half* __restrict__ Ch,
    int N, int K, int kend, int epi, int m0, int n0)
{
    const int tid = threadIdx.x, wid = tid >> 5, lane = tid & 31;
    const int nch = kend >> 6;
    const uint32_t sbase = smem_u32(smem);
    const int wm = wid >> 1, wn = wid & 1;

    float acc[2][8][4];
    #pragma unroll
    for (int mf = 0; mf < 2; mf++)
        #pragma unroll
        for (int nf = 0; nf < 8; nf++)
            #pragma unroll
            for (int c = 0; c < 4; c++) acc[mf][nf][c] = 0.f;

    issue_tile64(A, m0, K, 0, sbase,          tid);
    issue_tile64(B, n0, K, 0, sbase + TILE_B, tid);
    CP_COMMIT();

    const int a_row = wm * 32 + (lane & 15);
    const int a_col = ((lane >> 4) & 1) * 16;
    const int b_idx = lane >> 3;
    const int b_row = wn * 64 + ((b_idx >> 1) * 8) + (lane & 7);
    const int b_col = (b_idx & 1) * 16;

    for (int i = 0; i < nch; i++) {
        if (i + 1 < nch) {
            const uint32_t nbuf = sbase + ((i + 1) & 1) * STAGE_B;
            const int k1 = (i + 1) << 6;
            issue_tile64(A, m0, K, k1, nbuf,          tid);
            issue_tile64(B, n0, K, k1, nbuf + TILE_B, tid);
            CP_COMMIT();
            CP_WAIT1();
        } else {
            CP_WAIT0();
        }
        __syncthreads();

        const uint32_t buf = sbase + (i & 1) * STAGE_B;
        #pragma unroll
        for (int ks = 0; ks < 4; ks++) {
            const int kc = ks * 32;
            uint32_t a[2][4];
            ldsm_x4(buf + sw128(a_row * 128 + kc + a_col), a[0]);
            ldsm_x4(buf + sw128((a_row + 16) * 128 + kc + a_col), a[1]);
            #pragma unroll
            for (int p = 0; p < 4; p++) {
                uint32_t b[4];
                ldsm_x4(buf + TILE_B + sw128((b_row + p * 16) * 128 + kc + b_col), b);
                #pragma unroll
                for (int mf = 0; mf < 2; mf++)
                    #pragma unroll
                    for (int h = 0; h < 2; h++)
                        mma_f16(acc[mf][2 * p + h], a[mf], &b[2 * h]);
            }
        }
        __syncthreads();
    }

    const int em = m0 + wm * 32 + (lane >> 2);
    const int en = n0 + wn * 64 + (lane & 3) * 2;
    #pragma unroll
    for (int mf = 0; mf < 2; mf++) {
        #pragma unroll
        for (int nf = 0; nf < 8; nf++) {
            const int m = em + mf * 16;
            const int n = en + nf * 8;
            const float* d = acc[mf][nf];
            if (epi == 0) {
                float* r0 = C + (size_t)m * N + n;
                float* r1 = C + (size_t)(m + 8) * N + n;
                r0[0] = d[0]; r0[1] = d[1];
                r1[0] = d[2]; r1[1] = d[3];
            } else {
                __half2 h0; h0.x = __float2half(d[0]); h0.y = __float2half(d[1]);
                __half2 h1; h1.x = __float2half(d[2]); h1.y = __float2half(d[3]);
                *(__half2*)(Ch + (size_t)m * N + n) = h0;
                *(__half2*)(Ch + (size_t)(m + 8) * N + n) = h1;
            }
        }
    }
}

// generic GEMM kernel (scores + attnV).  mode: 1 causal tile-skip, 2 triangular K
__global__ void __launch_bounds__(256, 2) gemm_nt_f16(
    const __half* __restrict__ A, const __half* __restrict__ B,
    float* __restrict__ C, __half* __restrict__ Ch,
    int M, int N, int K, int mode, int epi)
{
    extern __shared__ char smem[];
    const int nb = blockIdx.x, mb = blockIdx.y;
    if (mode == 1 && nb > mb) return;
    const int m0 = mb * 128, n0 = nb * 128;
    const int kend = (mode == 2) ? (m0 + 128 < K ? m0 + 128 : K) : K;
    gemm_core(smem, A, B, C, Ch, N, K, kend, epi, m0, n0);
}

// fused projections: 1536 blocks -> q (0..511), k (512..1023), vT (1024..1535)
__global__ void __launch_bounds__(256, 2) proj_fused(
    const __half* __restrict__ x16,
    const __half* __restrict__ wq16, const __half* __restrict__ wk16,
    const __half* __restrict__ wv16,
    __half* __restrict__ q16, __half* __restrict__ k16, __half* __restrict__ vt16)
{
    extern __shared__ char smem[];
    const int id = blockIdx.x;
    const __half *A, *B;
    __half *Ch;
    int N, m0, n0;
    if (id < 1024) {
        const int z = id >> 9, r = id & 511;
        A = x16; B = z ? wk16 : wq16; Ch = z ? k16 : q16;
        N = D_DIM; n0 = (r & 15) * 128; m0 = (r >> 4) * 128;
    } else {
        const int r = id - 1024;
        A = wv16; B = x16; Ch = vt16;
        N = S_TOK; n0 = (r & 31) * 128; m0 = (r >> 5) * 128;
    }
    gemm_core(smem, A, B, nullptr, Ch, N, D_DIM, D_DIM, 1, m0, n0);
}

// ============================ merged fp32 -> fp16 convert =========================
#define XN4 ((size_t)S_TOK * D_DIM / 4)
#define WN4 ((size_t)D_DIM * D_DIM / 4)
__global__ __launch_bounds__(256) void conv_all(
    const float* __restrict__ x,  const float* __restrict__ wq,
    const float* __restrict__ wk, const float* __restrict__ wv,
    __half* __restrict__ xo, __half* __restrict__ qo,
    __half* __restrict__ ko, __half* __restrict__ vo)
{
    const size_t total = XN4 + 3 * WN4;
    size_t i = (size_t)blockIdx.x * 256 + threadIdx.x;
    const size_t stride = (size_t)gridDim.x * 256;
    for (; i < total; i += stride) {
        const float* src; __half* dst; size_t off;
        if (i < XN4)                  { src = x;  dst = xo; off = i; }
        else if (i < XN4 + WN4)       { src = wq; dst = qo; off = i - XN4; }
        else if (i < XN4 + 2 * WN4)   { src = wk; dst = ko; off = i - XN4 - WN4; }
        else                          { src = wv; dst = vo; off = i - XN4 - 2 * WN4; }
        float4 f = ((const float4*)src)[off];
        __half hv[4];
        hv[0] = __float2half(f.x); hv[1] = __float2half(f.y);
        hv[2] = __float2half(f.z); hv[3] = __float2half(f.w);
        ((uint2*)dst)[off] = *(uint2*)hv;
    }
}

// ============================ single-read softmax + dropout -> fp16 ===============
__global__ __launch_bounds__(256) void softmax_dropout_kernel(
    const float* __restrict__ scores, const float* __restrict__ drop_mask,
    __half* __restrict__ attn)
{
    const int i = blockIdx.x;
    const int tid = threadIdx.x;
    const int nvalid = i + 1;
    const float scale = rsqrtf((float)D_DIM);

    const float* row = scores + (size_t)i * S_TOK;
    const float* mrow = drop_mask + (size_t)i * S_TOK;
    __half* arow = attn + (size_t)i * S_TOK;

    float4 v[4];
    #pragma unroll
    for (int w = 0; w < 4; w++) {
        const int jb = (w * 256 + tid) * 4;
        if (jb < nvalid) v[w] = ((const float4*)row)[w * 256 + tid];
        else { v[w].x = v[w].y = v[w].z = v[w].w = -INFINITY; }
    }

    __shared__ float red[256];

    float lmax = -INFINITY;
    #pragma unroll
    for (int w = 0; w < 4; w++) {
        const int jb = (w * 256 + tid) * 4;
        const float* e = &v[w].x;
        #pragma unroll
        for (int c = 0; c < 4; c++)
            if (jb + c < nvalid) lmax = fmaxf(lmax, e[c] * scale);
    }
    red[tid] = lmax;
    __syncthreads();
    for (int s = 128; s > 0; s >>= 1) {
        if (tid < s) red[tid] = fmaxf(red[tid], red[tid + s]);
        __syncthreads();
    }
    const float m = red[0];
    __syncthreads();

    float lsum = 0.f;
    #pragma unroll
    for (int w = 0; w < 4; w++) {
        const int jb = (w * 256 + tid) * 4;
        const float* e = &v[w].x;
        #pragma unroll
        for (int c = 0; c < 4; c++)
            if (jb + c < nvalid) lsum += __expf(e[c] * scale - m);
    }
    red[tid] = lsum;
    __syncthreads();
    for (int s = 128; s > 0; s >>= 1) {
        if (tid < s) red[tid] += red[tid + s];
        __syncthreads();
    }
    const float inv_z = 1.0f / red[0];

    const int zend = (((i >> 7) + 1) << 7);
    #pragma unroll
    for (int w = 0; w < 4; w++) {
        const int jb = (w * 256 + tid) * 4;
        if (jb >= zend) continue;
        const float* e = &v[w].x;
        __half hv[4];
        #pragma unroll
        for (int c = 0; c < 4; c++) {
            const int j = jb + c;
            float out = 0.f;
            if (j < nvalid) out = __expf(e[c] * scale - m) * inv_z * mrow[j];
            hv[c] = __float2half(out);
        }
        *(uint2*)(arow + jb) = *(uint2*)hv;
    }
}

// =================================== launch =======================================
extern "C" void kernel_launch(void* const* d_in, const int* in_sizes, int n_in,
                              void* d_out, int out_size)
{
    const float* x  = (const float*)d_in[0];
    const float* Wq = (const float*)d_in[1];
    const float* Wk = (const float*)d_in[2];
    const float* Wv = (const float*)d_in[3];
    const float* dm = (const float*)d_in[4];
    float* out = (float*)d_out;

    __half *x16, *wq16, *wk16, *wv16, *q16, *k16, *vt16, *a16;
    float *sc;
    cudaGetSymbolAddress((void**)&x16,  g_x16);
    cudaGetSymbolAddress((void**)&wq16, g_wq16);
    cudaGetSymbolAddress((void**)&wk16, g_wk16);
    cudaGetSymbolAddress((void**)&wv16, g_wv16);
    cudaGetSymbolAddress((void**)&q16,  g_q16);
    cudaGetSymbolAddress((void**)&k16,  g_k16);
    cudaGetSymbolAddress((void**)&vt16, g_vt16);
    cudaGetSymbolAddress((void**)&a16,  g_a16);
    cudaGetSymbolAddress((void**)&sc,   g_sc);

    cudaFuncSetAttribute(gemm_nt_f16, cudaFuncAttributeMaxDynamicSharedMemorySize, GEMM_SMEM);
    cudaFuncSetAttribute(proj_fused,  cudaFuncAttributeMaxDynamicSharedMemorySize, GEMM_SMEM);

    // 0) convert inputs to fp16 (one merged launch)
    conv_all<<<2048, 256>>>(x, Wq, Wk, Wv, x16, wq16, wk16, wv16);

    // 1) fused projections: q = x@Wq^T, k = x@Wk^T, vT = Wv@x^T
    proj_fused<<<1536, 256, GEMM_SMEM>>>(x16, wq16, wk16, wv16, q16, k16, vt16);

    // 2) scores = q @ k^T (causal tile-skip, epi fp32)
    dim3 gScore(S_TOK / 128, S_TOK / 128);
    gemm_nt_f16<<<gScore, 256, GEMM_SMEM>>>(q16, k16, sc, nullptr,
                                            S_TOK, S_TOK, D_DIM, 1, 0);

    // 3) softmax + dropout -> attn fp16 (single-read, zero-padded to 128)
    softmax_dropout_kernel<<<S_TOK, 256>>>(sc, dm, a16);

    // 4) out = attn @ (vT)^T (triangular K, epi fp32)
    dim3 gOut(D_DIM / 128, S_TOK / 128);
    gemm_nt_f16<<<gOut, 256, GEMM_SMEM>>>(a16, vt16, out, nullptr,
                                          S_TOK, D_DIM, S_TOK, 2, 0);
}

// round 17
// speedup vs baseline: 3.2606x; 1.0344x over previous
#include <cuda_runtime.h>
#include <cuda_fp16.h>
#include <math.h>
#include <stdint.h>

#define S_TOK 4096
#define D_DIM 2048

// ---------------- scratch (no allocation allowed -> __device__ globals) ----------
__device__ __half g_x16[(size_t)S_TOK * D_DIM];
__device__ __half g_wq16[(size_t)D_DIM * D_DIM];
__device__ __half g_wk16[(size_t)D_DIM * D_DIM];
__device__ __half g_wv16[(size_t)D_DIM * D_DIM];
__device__ __half g_q16[(size_t)S_TOK * D_DIM];
__device__ __half g_k16[(size_t)S_TOK * D_DIM];
__device__ __half g_vt16[(size_t)D_DIM * S_TOK];   // vT [D, S]
__device__ float  g_sc[(size_t)S_TOK * S_TOK];     // scores fp32
__device__ __half g_a16[(size_t)S_TOK * S_TOK];    // attn fp16

// ============================ PTX helpers (base-arch only) ========================
__device__ __forceinline__ uint32_t smem_u32(const void* p) {
    uint32_t a;
    asm("{ .reg .u64 t; cvta.to.shared.u64 t, %1; cvt.u32.u64 %0, t; }" : "=r"(a) : "l"(p));
    return a;
}
#define CP_ASYNC16(dst, src) \
    asm volatile("cp.async.cg.shared.global [%0], [%1], 16;" :: "r"(dst), "l"(src) : "memory")
#define CP_COMMIT() asm volatile("cp.async.commit_group;" ::: "memory")
#define CP_WAIT1()  asm volatile("cp.async.wait_group 1;" ::: "memory")
#define CP_WAIT0()  asm volatile("cp.async.wait_group 0;" ::: "memory")

__device__ __forceinline__ void ldsm_x4(uint32_t addr, uint32_t* r) {
    asm volatile("ldmatrix.sync.aligned.m8n8.x4.shared.b16 {%0,%1,%2,%3}, [%4];"
                 : "=r"(r[0]), "=r"(r[1]), "=r"(r[2]), "=r"(r[3]) : "r"(addr));
}
__device__ __forceinline__ void mma_f16(float* d, const uint32_t* a, const uint32_t* b) {
    asm volatile(
        "mma.sync.aligned.m16n8k16.row.col.f32.f16.f16.f32 "
        "{%0,%1,%2,%3}, {%4,%5,%6,%7}, {%8,%9}, {%0,%1,%2,%3};"
        : "+f"(d[0]), "+f"(d[1]), "+f"(d[2]), "+f"(d[3])
        : "r"(a[0]), "r"(a[1]), "r"(a[2]), "r"(a[3]), "r"(b[0]), "r"(b[1]));
}
__device__ __forceinline__ uint32_t sw128(uint32_t off) { return off ^ ((off >> 3) & 0x70); }

// ============================ fp16 NT GEMM core ===================================
// Tile 128x128, K-chunk 64, 3-stage cp.async pipeline, single barrier per chunk.
// 32KB/stage -> 96KB smem, 2 CTAs/SM.
#define KC       64
#define TILE_B   16384               // 128 rows x 64 fp16 (128B/row)
#define STAGE_B  (2 * TILE_B)        // A, B = 32KB
#define NSTAGE   3
#define GEMM_SMEM (NSTAGE * STAGE_B) // 96KB

__device__ __forceinline__ void issue_tile64(const __half* __restrict__ g,
                                             int row0, int ld, int k0,
                                             uint32_t sbase, int tid) {
    #pragma unroll
    for (int it = 0; it < 4; it++) {
        int u = tid + it * 256;          // 0..1023 16-byte units
        int r = u >> 3, s = u & 7;
        CP_ASYNC16(sbase + sw128(r * 128 + s * 16),
                   g + (size_t)(row0 + r) * ld + k0 + s * 8);
    }
}

// C[M,N] = A[M,K] * B[N,K]^T over k in [0, kend). epi: 0 -> fp32 C, 1 -> fp16 Ch.
__device__ __forceinline__ void gemm_core(
    char* smem,
    const __half* __restrict__ A, const __half* __restrict__ B,
    float* __restrict__ C, __half* __restrict__ Ch,
    int N, int K, int kend, int epi, int m0, int n0)
{
    const int tid = threadIdx.x, wid = tid >> 5, lane = tid & 31;
    const int nch = kend >> 6;          // >= 2 always
    const uint32_t sbase = smem_u32(smem);
    const int wm = wid >> 1, wn = wid & 1;

    float acc[2][8][4];
    #pragma unroll
    for (int mf = 0; mf < 2; mf++)
        #pragma unroll
        for (int nf = 0; nf < 8; nf++)
            #pragma unroll
            for (int c = 0; c < 4; c++) acc[mf][nf][c] = 0.f;

    // prologue: chunks 0,1 into stages 0,1
    #pragma unroll
    for (int pre = 0; pre < 2; pre++) {
        const uint32_t st = sbase + pre * STAGE_B;
        issue_tile64(A, m0, K, pre * KC, st,          tid);
        issue_tile64(B, n0, K, pre * KC, st + TILE_B, tid);
        CP_COMMIT();
    }

    const int a_row = wm * 32 + (lane & 15);
    const int a_col = ((lane >> 4) & 1) * 16;
    const int b_idx = lane >> 3;
    const int b_row = wn * 64 + ((b_idx >> 1) * 8) + (lane & 7);
    const int b_col = (b_idx & 1) * 16;

    for (int i = 0; i < nch; i++) {
        if (i == nch - 1) { CP_WAIT0(); } else { CP_WAIT1(); }
        __syncthreads();
        // single barrier: stage (i+2)%3 == (i-1)%3 fully consumed before this barrier
        if (i + 2 < nch) {
            const uint32_t st = sbase + ((i + 2) % NSTAGE) * STAGE_B;
            const int k2 = (i + 2) * KC;
            issue_tile64(A, m0, K, k2, st,          tid);
            issue_tile64(B, n0, K, k2, st + TILE_B, tid);
            CP_COMMIT();
        }

        const uint32_t buf = sbase + (i % NSTAGE) * STAGE_B;
        #pragma unroll
        for (int ks = 0; ks < 4; ks++) {
            const int kc = ks * 32;
            uint32_t a[2][4];
            ldsm_x4(buf + sw128(a_row * 128 + kc + a_col), a[0]);
            ldsm_x4(buf + sw128((a_row + 16) * 128 + kc + a_col), a[1]);
            #pragma unroll
            for (int p = 0; p < 4; p++) {
                uint32_t b[4];
                ldsm_x4(buf + TILE_B + sw128((b_row + p * 16) * 128 + kc + b_col), b);
                #pragma unroll
                for (int mf = 0; mf < 2; mf++)
                    #pragma unroll
                    for (int h = 0; h < 2; h++)
                        mma_f16(acc[mf][2 * p + h], a[mf], &b[2 * h]);
            }
        }
    }

    const int em = m0 + wm * 32 + (lane >> 2);
    const int en = n0 + wn * 64 + (lane & 3) * 2;
    #pragma unroll
    for (int mf = 0; mf < 2; mf++) {
        #pragma unroll
        for (int nf = 0; nf < 8; nf++) {
            const int m = em + mf * 16;
            const int n = en + nf * 8;
            const float* d = acc[mf][nf];
            if (epi == 0) {
                float* r0 = C + (size_t)m * N + n;
                float* r1 = C + (size_t)(m + 8) * N + n;
                r0[0] = d[0]; r0[1] = d[1];
                r1[0] = d[2]; r1[1] = d[3];
            } else {
                __half2 h0; h0.x = __float2half(d[0]); h0.y = __float2half(d[1]);
                __half2 h1; h1.x = __float2half(d[2]); h1.y = __float2half(d[3]);
                *(__half2*)(Ch + (size_t)m * N + n) = h0;
                *(__half2*)(Ch + (size_t)(m + 8) * N + n) = h1;
            }
        }
    }
}

// ---- stage 1: fused q/k projections: 1024 blocks -> q (0..511), k (512..1023) ----
__global__ void __launch_bounds__(256, 2) proj_qk(
    const __half* __restrict__ x16,
    const __half* __restrict__ wq16, const __half* __restrict__ wk16,
    __half* __restrict__ q16, __half* __restrict__ k16)
{
    extern __shared__ char smem[];
    const int id = blockIdx.x;
    const int z = id >> 9, r = id & 511;
    const __half* B = z ? wk16 : wq16;
    __half* Ch = z ? k16 : q16;
    const int m0 = (r >> 4) * 128, n0 = (r & 15) * 128;
    gemm_core(smem, x16, B, nullptr, Ch, D_DIM, D_DIM, D_DIM, 1, m0, n0);
}

// ---- stage 2: merged scores (causal) + vT projection, one launch ----------------
// id 0..1023: scores tile (mb=id>>5, nb=id&31), exit if nb>mb.
// id 1024..1535: vT tile (r = id-1024): vT = Wv @ x^T, [D, S].
__global__ void __launch_bounds__(256, 2) scores_projv(
    const __half* __restrict__ q16, const __half* __restrict__ k16,
    const __half* __restrict__ wv16, const __half* __restrict__ x16,
    float* __restrict__ sc, __half* __restrict__ vt16)
{
    extern __shared__ char smem[];
    const int id = blockIdx.x;
    if (id < 1024) {
        const int mb = id >> 5, nb = id & 31;
        if (nb > mb) return;
        gemm_core(smem, q16, k16, sc, nullptr, S_TOK, D_DIM, D_DIM, 0,
                  mb * 128, nb * 128);
    } else {
        const int r = id - 1024;
        gemm_core(smem, wv16, x16, nullptr, vt16, S_TOK, D_DIM, D_DIM, 1,
                  (r >> 5) * 128, (r & 31) * 128);
    }
}

// ---- stage 4: out = attn @ vT^T, triangular K, longest rows scheduled first -----
__global__ void __launch_bounds__(256, 2) attnv_f16(
    const __half* __restrict__ a16, const __half* __restrict__ vt16,
    float* __restrict__ out)
{
    extern __shared__ char smem[];
    const int mb = (S_TOK / 128 - 1) - blockIdx.y;   // reversed: longest first
    const int nb = blockIdx.x;
    const int m0 = mb * 128, n0 = nb * 128;
    const int kend = (m0 + 128 < S_TOK) ? m0 + 128 : S_TOK;
    gemm_core(smem, a16, vt16, out, nullptr, D_DIM, S_TOK, kend, 0, m0, n0);
}

// ============================ merged fp32 -> fp16 convert =========================
#define XN4 ((size_t)S_TOK * D_DIM / 4)
#define WN4 ((size_t)D_DIM * D_DIM / 4)
__global__ __launch_bounds__(256) void conv_all(
    const float* __restrict__ x,  const float* __restrict__ wq,
    const float* __restrict__ wk, const float* __restrict__ wv,
    __half* __restrict__ xo, __half* __restrict__ qo,
    __half* __restrict__ ko, __half* __restrict__ vo)
{
    const size_t total = XN4 + 3 * WN4;
    size_t i = (size_t)blockIdx.x * 256 + threadIdx.x;
    const size_t stride = (size_t)gridDim.x * 256;
    for (; i < total; i += stride) {
        const float* src; __half* dst; size_t off;
        if (i < XN4)                  { src = x;  dst = xo; off = i; }
        else if (i < XN4 + WN4)       { src = wq; dst = qo; off = i - XN4; }
        else if (i < XN4 + 2 * WN4)   { src = wk; dst = ko; off = i - XN4 - WN4; }
        else                          { src = wv; dst = vo; off = i - XN4 - 2 * WN4; }
        float4 f = ((const float4*)src)[off];
        __half hv[4];
        hv[0] = __float2half(f.x); hv[1] = __float2half(f.y);
        hv[2] = __float2half(f.z); hv[3] = __float2half(f.w);
        ((uint2*)dst)[off] = *(uint2*)hv;
    }
}

// ============================ single-read softmax + dropout -> fp16 ===============
__global__ __launch_bounds__(256) void softmax_dropout_kernel(
    const float* __restrict__ scores, const float* __restrict__ drop_mask,
    __half* __restrict__ attn)
{
    const int i = blockIdx.x;
    const int tid = threadIdx.x;
    const int nvalid = i + 1;
    const float scale = rsqrtf((float)D_DIM);

    const float* row = scores + (size_t)i * S_TOK;
    const float* mrow = drop_mask + (size_t)i * S_TOK;
    __half* arow = attn + (size_t)i * S_TOK;

    float4 v[4];
    #pragma unroll
    for (int w = 0; w < 4; w++) {
        const int jb = (w * 256 + tid) * 4;
        if (jb < nvalid) v[w] = ((const float4*)row)[w * 256 + tid];
        else { v[w].x = v[w].y = v[w].z = v[w].w = -INFINITY; }
    }

    __shared__ float red[256];

    float lmax = -INFINITY;
    #pragma unroll
    for (int w = 0; w < 4; w++) {
        const int jb = (w * 256 + tid) * 4;
        const float* e = &v[w].x;
        #pragma unroll
        for (int c = 0; c < 4; c++)
            if (jb + c < nvalid) lmax = fmaxf(lmax, e[c] * scale);
    }
    red[tid] = lmax;
    __syncthreads();
    for (int s = 128; s > 0; s >>= 1) {
        if (tid < s) red[tid] = fmaxf(red[tid], red[tid + s]);
        __syncthreads();
    }
    const float m = red[0];
    __syncthreads();

    float lsum = 0.f;
    #pragma unroll
    for (int w = 0; w < 4; w++) {
        const int jb = (w * 256 + tid) * 4;
        const float* e = &v[w].x;
        #pragma unroll
        for (int c = 0; c < 4; c++)
            if (jb + c < nvalid) lsum += __expf(e[c] * scale - m);
    }
    red[tid] = lsum;
    __syncthreads();
    for (int s = 128; s > 0; s >>= 1) {
        if (tid < s) red[tid] += red[tid + s];
        __syncthreads();
    }
    const float inv_z = 1.0f / red[0];

    const int zend = (((i >> 7) + 1) << 7);
    #pragma unroll
    for (int w = 0; w < 4; w++) {
        const int jb = (w * 256 + tid) * 4;
        if (jb >= zend) continue;
        const float* e = &v[w].x;
        __half hv[4];
        #pragma unroll
        for (int c = 0; c < 4; c++) {
            const int j = jb + c;
            float out = 0.f;
            if (j < nvalid) out = __expf(e[c] * scale - m) * inv_z * mrow[j];
            hv[c] = __float2half(out);
        }
        *(uint2*)(arow + jb) = *(uint2*)hv;
    }
}

// =================================== launch =======================================
extern "C" void kernel_launch(void* const* d_in, const int* in_sizes, int n_in,
                              void* d_out, int out_size)
{
    const float* x  = (const float*)d_in[0];
    const float* Wq = (const float*)d_in[1];
    const float* Wk = (const float*)d_in[2];
    const float* Wv = (const float*)d_in[3];
    const float* dm = (const float*)d_in[4];
    float* out = (float*)d_out;

    __half *x16, *wq16, *wk16, *wv16, *q16, *k16, *vt16, *a16;
    float *sc;
    cudaGetSymbolAddress((void**)&x16,  g_x16);
    cudaGetSymbolAddress((void**)&wq16, g_wq16);
    cudaGetSymbolAddress((void**)&wk16, g_wk16);
    cudaGetSymbolAddress((void**)&wv16, g_wv16);
    cudaGetSymbolAddress((void**)&q16,  g_q16);
    cudaGetSymbolAddress((void**)&k16,  g_k16);
    cudaGetSymbolAddress((void**)&vt16, g_vt16);
    cudaGetSymbolAddress((void**)&a16,  g_a16);
    cudaGetSymbolAddress((void**)&sc,   g_sc);

    cudaFuncSetAttribute(proj_qk,      cudaFuncAttributeMaxDynamicSharedMemorySize, GEMM_SMEM);
    cudaFuncSetAttribute(scores_projv, cudaFuncAttributeMaxDynamicSharedMemorySize, GEMM_SMEM);
    cudaFuncSetAttribute(attnv_f16,    cudaFuncAttributeMaxDynamicSharedMemorySize, GEMM_SMEM);

    // 0) convert inputs to fp16 (one merged launch)
    conv_all<<<2048, 256>>>(x, Wq, Wk, Wv, x16, wq16, wk16, wv16);

    // 1) q = x@Wq^T, k = x@Wk^T
    proj_qk<<<1024, 256, GEMM_SMEM>>>(x16, wq16, wk16, q16, k16);

    // 2) scores = q@k^T (causal) + vT = Wv@x^T, merged (vT fills scores' tail)
    scores_projv<<<1536, 256, GEMM_SMEM>>>(q16, k16, wv16, x16, sc, vt16);

    // 3) softmax + dropout -> attn fp16 (single-read, zero-padded to 128)
    softmax_dropout_kernel<<<S_TOK, 256>>>(sc, dm, a16);

    // 4) out = attn @ vT^T (triangular K, longest rows first)
    dim3 gOut(D_DIM / 128, S_TOK / 128);
    attnv_f16<<<gOut, 256, GEMM_SMEM>>>(a16, vt16, out);
}